// round 13
// baseline (speedup 1.0000x reference)
#include <cuda_runtime.h>
#include <cstdint>

// Problem constants (fixed shapes from reference)
#define BB 2
#define TT 2048
#define DD 512
#define HH 8
#define DH 64
#define SCALE 0.125f   // 64^-0.5

// Scratch: Qp (conv folded into query, scale folded), bias dots, and the
// materialized softmax weight matrix W[b,q,h,t] (268 MB -- HBM is idle).
__device__ float g_Qp[BB * TT * DD];                  // 8.4 MB
__device__ float g_bq[BB * TT * HH];
__device__ float g_W[(size_t)BB * TT * HH * TT];      // 268 MB

typedef unsigned long long u64;

__device__ __forceinline__ u64 ffma2(u64 a, u64 b, u64 c) {
    u64 d;
    asm("fma.rn.f32x2 %0, %1, %2, %3;" : "=l"(d) : "l"(a), "l"(b), "l"(c));
    return d;
}
__device__ __forceinline__ float2 unpk(u64 a) {
    float2 r;
    asm("mov.b64 {%0,%1}, %2;" : "=f"(r.x), "=f"(r.y) : "l"(a));
    return r;
}
__device__ __forceinline__ u64 pk2(float x) {
    u64 r;
    asm("mov.b64 %0, {%1,%1};" : "=l"(r) : "f"(x));
    return r;
}
__device__ __forceinline__ uint32_t smem_u32(const void* p) {
    uint32_t a;
    asm("{ .reg .u64 t; cvta.to.shared.u64 t, %1; cvt.u32.u64 %0, t; }"
        : "=r"(a) : "l"(p));
    return a;
}
__device__ __forceinline__ void cp16(uint32_t dst, const void* src) {
    asm volatile("cp.async.cg.shared.global [%0], [%1], 16;" :: "r"(dst), "l"(src));
}
#define CP_COMMIT()  asm volatile("cp.async.commit_group;")
#define CP_WAIT(N)   asm volatile("cp.async.wait_group %0;" :: "n"(N))

// ---------------------------------------------------------------------------
// Kernel 1: Qp[row, h*64+d] = SCALE * sum_j query[row, h*64+j] * conv_w[h*64+j, d]
//           bq[row, h]      = SCALE * sum_j query[row, h*64+j] * conv_b[h*64+j]
// ---------------------------------------------------------------------------
#define TQ1 16
__global__ __launch_bounds__(256) void prep_kernel(
    const float* __restrict__ query,
    const float* __restrict__ conv_w,
    const float* __restrict__ conv_b)
{
    __shared__ __align__(16) float q_sh[TQ1][DD];   // 32 KB
    const int q0 = blockIdx.x * TQ1;                // row base in [0, B*T)
    const int t  = threadIdx.x;

    const float4* qg = (const float4*)(query + (size_t)q0 * DD);
    float4* qs = (float4*)&q_sh[0][0];
    #pragma unroll
    for (int i = 0; i < TQ1 * DD / 4 / 256; ++i)    // 8
        qs[t + i * 256] = qg[t + i * 256];
    __syncthreads();

    // bias dot terms (conv_b is zero in this dataset, but keep it general)
    if (t < TQ1 * HH) {                             // 128 threads
        int q = t >> 3, h = t & 7;
        float acc = 0.f;
        #pragma unroll
        for (int j = 0; j < DH; ++j)
            acc += q_sh[q][h * DH + j] * __ldg(conv_b + h * DH + j);
        g_bq[(q0 + q) * HH + h] = SCALE * acc;
    }

    #pragma unroll 1
    for (int cc = 0; cc < 2; ++cc) {
        int c = t + cc * 256;                       // output column 0..511
        int h = c >> 6;
        float W[DH];
        #pragma unroll
        for (int j = 0; j < DH; ++j)
            W[j] = __ldg(conv_w + (h * DH + j) * DH + (c & 63));
        #pragma unroll 1
        for (int q = 0; q < TQ1; ++q) {
            const float4* qr = (const float4*)&q_sh[q][h * DH];
            float acc = 0.f;
            #pragma unroll
            for (int i = 0; i < 16; ++i) {
                float4 v = qr[i];
                acc += W[4*i+0] * v.x + W[4*i+1] * v.y
                     + W[4*i+2] * v.z + W[4*i+3] * v.w;
            }
            g_Qp[(size_t)(q0 + q) * DD + c] = SCALE * acc;
        }
    }
}

// ---------------------------------------------------------------------------
// Kernel A: scores + head-softmax -> W[b,q,h,t].
// Block = 512 threads = 16 q x 32 t-groups; thread owns ALL 8 heads of its
// 4 (spread) t's -> softmax is thread-local: NO shuffles, exp only in the
// one-time epilogue. Inner d-loop: 8 broadcast Qp LDS.128 + 4 conflict-free
// V LDS.128 per 64 ffma2 (intensity 5.3), 32 independent acc chains.
// SMEM: Qp tile 16x512 (32KB) + V tile 128x64 padded to 68 (34KB) + bq.
// ---------------------------------------------------------------------------
#define ATQ 16
#define ATT 128
#define VPAD 68
#define A_SMEM ((ATQ*DD + ATT*VPAD + ATQ*HH) * 4)

__global__ __launch_bounds__(512, 1) void score_kernel(
    const float* __restrict__ value)
{
    extern __shared__ __align__(16) float sm[];
    float* qp_sh = sm;                     // [16][512]
    float* v_sh  = sm + ATQ * DD;          // [128][68]
    float* bq_sh = v_sh + ATT * VPAD;      // [16*8]

    const int b   = blockIdx.z;
    const int q0  = blockIdx.y * ATQ;
    const int t0  = blockIdx.x * ATT;
    const int tid = threadIdx.x;
    const int qe  = tid >> 5;              // q_local 0..15 (one warp per q)
    const int tg  = tid & 31;              // t-group 0..31; owns t = t0+tg+32j

    // Stage Qp tile (rows q0..q0+15 are contiguous: 32KB)
    {
        const float4* src = (const float4*)(g_Qp + (size_t)(b * TT + q0) * DD);
        float4* dst = (float4*)qp_sh;
        #pragma unroll
        for (int i = 0; i < 4; ++i) dst[tid + i * 512] = src[tid + i * 512];
    }
    // Stage V tile (128 x 64 -> padded stride 68)
    {
        const float4* src = (const float4*)(value + (size_t)(b * TT + t0) * DH);
        #pragma unroll
        for (int i = 0; i < 4; ++i) {
            int idx = tid + i * 512;       // 0..2047 float4s
            int r = idx >> 4, c4 = idx & 15;
            *(float4*)(v_sh + r * VPAD + c4 * 4) = src[idx];
        }
    }
    if (tid < ATQ * HH) bq_sh[tid] = g_bq[(b * TT + q0) * HH + tid];
    __syncthreads();

    u64 acc[HH][4];
    #pragma unroll
    for (int h = 0; h < HH; ++h)
        #pragma unroll
        for (int j = 0; j < 4; ++j) acc[h][j] = 0ULL;

    const float* qrow = qp_sh + qe * DD;

    #pragma unroll 1
    for (int dd = 0; dd < DH; dd += 4) {
        u64 vf[4][2];
        #pragma unroll
        for (int j = 0; j < 4; ++j) {       // spread t: conflict-free LDS.128
            longlong2 vv = *(const longlong2*)(v_sh + (tg + 32 * j) * VPAD + dd);
            vf[j][0] = (u64)vv.x;  vf[j][1] = (u64)vv.y;
        }
        #pragma unroll
        for (int h = 0; h < HH; ++h) {
            longlong2 qv = *(const longlong2*)(qrow + h * DH + dd);  // broadcast
            u64 qa = (u64)qv.x, qb = (u64)qv.y;
            #pragma unroll
            for (int j = 0; j < 4; ++j) {
                acc[h][j] = ffma2(qa, vf[j][0], acc[h][j]);
                acc[h][j] = ffma2(qb, vf[j][1], acc[h][j]);
            }
        }
    }

    // Epilogue: thread-local softmax over the 8 heads for each of 4 t's
    float w[HH][4];
    #pragma unroll
    for (int h = 0; h < HH; ++h) {
        float bqv = bq_sh[qe * HH + h];
        #pragma unroll
        for (int j = 0; j < 4; ++j) {
            float2 p = unpk(acc[h][j]);
            w[h][j] = p.x + p.y + bqv;
        }
    }
    #pragma unroll
    for (int j = 0; j < 4; ++j) {
        float sum = 0.f;
        #pragma unroll
        for (int h = 0; h < HH; ++h) { w[h][j] = __expf(w[h][j]); sum += w[h][j]; }
        float rinv = __fdividef(1.f, sum);
        #pragma unroll
        for (int h = 0; h < HH; ++h) w[h][j] *= rinv;
    }
    // Store W[((b*TT+q)*HH+h)*TT + t], t = t0 + tg + 32j (coalesced per (h,j))
    {
        size_t base = ((size_t)(b * TT + q0 + qe) * HH) * TT + t0 + tg;
        #pragma unroll
        for (int h = 0; h < HH; ++h)
            #pragma unroll
            for (int j = 0; j < 4; ++j)
                g_W[base + (size_t)h * TT + 32 * j] = w[h][j];
    }
}

// ---------------------------------------------------------------------------
// Kernel B: ctx = W x V  (per batch: M=16384 rows (q,h), K=2048 t, N=64 d).
// Pure fp32x2 GEMM, no softmax anywhere. Block = 256 threads = 32 row-groups
// x 8 d-groups; thread owns 4 spread rows (rg+32i) x 8 d (4 f32x2 accs).
// K-loop: 32 chunks of 64 t, W/V tiles double-buffered via cp.async.
// ---------------------------------------------------------------------------
#define BMR 128
#define BKT 64
#define B_SMEM ((2 * BMR * VPAD + 2 * BKT * VPAD) * 4)

__global__ __launch_bounds__(256, 2) void ctx_kernel(
    const float* __restrict__ value,
    float* __restrict__ out)
{
    extern __shared__ __align__(16) float sm[];
    float* wbuf0 = sm;                       // [128][68]
    float* wbuf1 = sm + BMR * VPAD;
    float* vbuf0 = sm + 2 * BMR * VPAD;      // [64][68]
    float* vbuf1 = vbuf0 + BKT * VPAD;

    const int b   = blockIdx.y;
    const int rb  = blockIdx.x * BMR;        // row base in [0, 16384)
    const int tid = threadIdx.x;
    const int rg  = tid >> 3;                // 0..31; rows rg + 32i
    const int dg  = tid & 7;                 // 0..7;  d = dg*8 .. dg*8+7
    const int dbase = dg * 8;

    const uint32_t wS[2] = { smem_u32(wbuf0), smem_u32(wbuf1) };
    const uint32_t vS[2] = { smem_u32(vbuf0), smem_u32(vbuf1) };
    const float* wb_[2] = { wbuf0, wbuf1 };
    const float* vb_[2] = { vbuf0, vbuf1 };

    const char* wsrc = (const char*)(g_W + ((size_t)b * TT * HH + rb) * TT);
    const char* vsrc = (const char*)(value + (size_t)b * TT * DH);

    u64 acc[4][4];
    #pragma unroll
    for (int i = 0; i < 4; ++i)
        #pragma unroll
        for (int p = 0; p < 4; ++p) acc[i][p] = 0ULL;

    // Stage chunk 0
    #pragma unroll
    for (int i = 0; i < 8; ++i) {
        int idx = tid + i * 256;  int r = idx >> 4, c4 = idx & 15;
        cp16(wS[0] + (r * VPAD + c4 * 4) * 4, wsrc + ((size_t)r * TT + c4 * 4) * 4);
    }
    #pragma unroll
    for (int i = 0; i < 4; ++i) {
        int idx = tid + i * 256;  int r = idx >> 4, c4 = idx & 15;
        cp16(vS[0] + (r * VPAD + c4 * 4) * 4, vsrc + ((size_t)r * DH + c4 * 4) * 4);
    }
    CP_COMMIT();

    #pragma unroll 1
    for (int c = 0; c < TT / BKT; ++c) {
        if (c + 1 < TT / BKT) {
            int bi = (c + 1) & 1;
            const char* wc = wsrc + (size_t)(c + 1) * BKT * 4;
            const char* vc = vsrc + (size_t)(c + 1) * BKT * DH * 4;
            #pragma unroll
            for (int i = 0; i < 8; ++i) {
                int idx = tid + i * 256;  int r = idx >> 4, c4 = idx & 15;
                cp16(wS[bi] + (r * VPAD + c4 * 4) * 4, wc + ((size_t)r * TT + c4 * 4) * 4);
            }
            #pragma unroll
            for (int i = 0; i < 4; ++i) {
                int idx = tid + i * 256;  int r = idx >> 4, c4 = idx & 15;
                cp16(vS[bi] + (r * VPAD + c4 * 4) * 4, vc + ((size_t)r * DH + c4 * 4) * 4);
            }
            CP_COMMIT();
            CP_WAIT(1);
        } else {
            CP_WAIT(0);
        }
        __syncthreads();

        const float* wb = wb_[c & 1];
        const float* vb = vb_[c & 1];

        #pragma unroll 2
        for (int t = 0; t < BKT; ++t) {
            longlong2 v0 = *(const longlong2*)(vb + t * VPAD + dbase);
            longlong2 v1 = *(const longlong2*)(vb + t * VPAD + dbase + 4);
            u64 vf0 = (u64)v0.x, vf1 = (u64)v0.y, vf2 = (u64)v1.x, vf3 = (u64)v1.y;
            #pragma unroll
            for (int i = 0; i < 4; ++i) {
                u64 wv = pk2(wb[(rg + 32 * i) * VPAD + t]);
                acc[i][0] = ffma2(wv, vf0, acc[i][0]);
                acc[i][1] = ffma2(wv, vf1, acc[i][1]);
                acc[i][2] = ffma2(wv, vf2, acc[i][2]);
                acc[i][3] = ffma2(wv, vf3, acc[i][3]);
            }
        }
        __syncthreads();
    }

    // out[(b*16384 + rb + row)*64 + d]; d-pairs are consecutive floats
    #pragma unroll
    for (int i = 0; i < 4; ++i) {
        size_t ofs = ((size_t)b * TT * HH + rb + rg + 32 * i) * (size_t)DH + dbase;
        longlong2 s0, s1;
        s0.x = (long long)acc[i][0];  s0.y = (long long)acc[i][1];
        s1.x = (long long)acc[i][2];  s1.y = (long long)acc[i][3];
        *(longlong2*)(out + ofs)     = s0;
        *(longlong2*)(out + ofs + 4) = s1;
    }
}

extern "C" void kernel_launch(void* const* d_in, const int* in_sizes, int n_in,
                              void* d_out, int out_size) {
    const float* query  = (const float*)d_in[0];   // [2,2048,512]
    const float* value  = (const float*)d_in[1];   // [2,2048,64]
    const float* conv_w = (const float*)d_in[2];   // [512,64,1]
    const float* conv_b = (const float*)d_in[3];   // [512]
    float* out = (float*)d_out;                    // [2,2048,512]

    cudaFuncSetAttribute(score_kernel,
                         cudaFuncAttributeMaxDynamicSharedMemorySize, A_SMEM);
    cudaFuncSetAttribute(ctx_kernel,
                         cudaFuncAttributeMaxDynamicSharedMemorySize, B_SMEM);

    prep_kernel<<<BB * TT / TQ1, 256>>>(query, conv_w, conv_b);
    score_kernel<<<dim3(TT / ATT, TT / ATQ, BB), 512, A_SMEM>>>(value);
    ctx_kernel<<<dim3(TT * HH / BMR, BB), 256, B_SMEM>>>(value, out);
}

// round 14
// speedup vs baseline: 1.1606x; 1.1606x over previous
#include <cuda_runtime.h>
#include <cstdint>

// Problem constants (fixed shapes from reference)
#define BB 2
#define TT 2048
#define DD 512
#define HH 8
#define DH 64
#define SCALE 0.125f   // 64^-0.5

// Scratch: Qp[b,q,h,d] (conv folded into query, scale folded), bias dot per (b,q,h)
__device__ float g_Qp[BB * TT * DD];   // 8.4 MB
__device__ float g_bq[BB * TT * HH];

typedef unsigned long long u64;

__device__ __forceinline__ u64 ffma2(u64 a, u64 b, u64 c) {
    u64 d;
    asm("fma.rn.f32x2 %0, %1, %2, %3;" : "=l"(d) : "l"(a), "l"(b), "l"(c));
    return d;
}
__device__ __forceinline__ float2 unpk(u64 a) {
    float2 r;
    asm("mov.b64 {%0,%1}, %2;" : "=f"(r.x), "=f"(r.y) : "l"(a));
    return r;
}
__device__ __forceinline__ u64 pk2(float x) {
    u64 r;
    asm("mov.b64 %0, {%1,%1};" : "=l"(r) : "f"(x));
    return r;
}
__device__ __forceinline__ uint32_t smem_u32(const void* p) {
    uint32_t a;
    asm("{ .reg .u64 t; cvta.to.shared.u64 t, %1; cvt.u32.u64 %0, t; }"
        : "=r"(a) : "l"(p));
    return a;
}
__device__ __forceinline__ void cp16(uint32_t dst, const void* src) {
    asm volatile("cp.async.cg.shared.global [%0], [%1], 16;" :: "r"(dst), "l"(src));
}
#define CP_COMMIT()  asm volatile("cp.async.commit_group;")
#define CP_WAIT(N)   asm volatile("cp.async.wait_group %0;" :: "n"(N))

// ---------------------------------------------------------------------------
// Kernel 1: Qp[row, h*64+d] = SCALE * sum_j query[row, h*64+j] * conv_w[h*64+j, d]
//           bq[row, h]      = SCALE * sum_j query[row, h*64+j] * conv_b[h*64+j]
// ---------------------------------------------------------------------------
#define TQ1 16
__global__ __launch_bounds__(256) void prep_kernel(
    const float* __restrict__ query,
    const float* __restrict__ conv_w,
    const float* __restrict__ conv_b)
{
    __shared__ __align__(16) float q_sh[TQ1][DD];   // 32 KB
    const int q0 = blockIdx.x * TQ1;                // row base in [0, B*T)
    const int t  = threadIdx.x;

    const float4* qg = (const float4*)(query + (size_t)q0 * DD);
    float4* qs = (float4*)&q_sh[0][0];
    #pragma unroll
    for (int i = 0; i < TQ1 * DD / 4 / 256; ++i)    // 8
        qs[t + i * 256] = qg[t + i * 256];
    __syncthreads();

    // bias dot terms (conv_b is zero in this dataset, but keep it general)
    if (t < TQ1 * HH) {                             // 128 threads
        int q = t >> 3, h = t & 7;
        float acc = 0.f;
        #pragma unroll
        for (int j = 0; j < DH; ++j)
            acc += q_sh[q][h * DH + j] * __ldg(conv_b + h * DH + j);
        g_bq[(q0 + q) * HH + h] = SCALE * acc;
    }

    #pragma unroll 1
    for (int cc = 0; cc < 2; ++cc) {
        int c = t + cc * 256;                       // output column 0..511
        int h = c >> 6;
        float W[DH];
        #pragma unroll
        for (int j = 0; j < DH; ++j)
            W[j] = __ldg(conv_w + (h * DH + j) * DH + (c & 63));
        #pragma unroll 1
        for (int q = 0; q < TQ1; ++q) {
            const float4* qr = (const float4*)&q_sh[q][h * DH];
            float acc = 0.f;
            #pragma unroll
            for (int i = 0; i < 16; ++i) {
                float4 v = qr[i];
                acc += W[4*i+0] * v.x + W[4*i+1] * v.y
                     + W[4*i+2] * v.z + W[4*i+3] * v.w;
            }
            g_Qp[(size_t)(q0 + q) * DD + c] = SCALE * acc;
        }
    }
}

// ---------------------------------------------------------------------------
// Kernel 2: fused scores + head-softmax + context, 2 q-rows per warp.
// R9 structure (best: 543us) + ANTI-LOCKSTEP SKEW: co-SMSP warps run
// byte-identical streams and re-sync at every tile barrier, so their ~250cyc
// serial softmax chains align and the fma pipe idles (measured: 1024 busy /
// 2015 wall = 51%). After each tile barrier, warp slot d = (ql>>2) +
// 2*(blockIdx.x&1) runs a d*16-iteration dependent-FMA delay (~230cyc/step),
// phase-shifting co-resident warps so one warp's chain hides under another's
// FMA burst. Skew cost <= 2.3% per tile; potential gain ~35%.
// Lane layout: h = bits[2:0] (softmax group), e = bits[4:3] (d-quarter /
// key-slot). Lane e owns 16B d-chunks c == e (mod 4): conflict-free LDS.128.
// V tiles (64 keys x 64 d) double-buffered in SMEM via cp.async.
// ---------------------------------------------------------------------------
#define TQ 16
#define KT 64
#define NTILES (TT / KT)

// Phase A: partial dots of 4 keys for both q-rows (V loaded once per chunk)
__device__ __forceinline__ void dots4(
    const longlong2* __restrict__ Vs, int tt0, int e,
    const u64* __restrict__ qpa, const u64* __restrict__ qpb,
    float* __restrict__ pa, float* __restrict__ pb)
{
    #pragma unroll
    for (int j = 0; j < 4; ++j) {
        const longlong2* vr = Vs + (tt0 + j) * 16;
        u64 a0 = 0ULL, a1 = 0ULL, b0 = 0ULL, b1 = 0ULL;
        #pragma unroll
        for (int i = 0; i < 4; ++i) {
            longlong2 vq = vr[i * 4 + e];   // one LDS.128, 4 ffma2
            a0 = ffma2(qpa[2*i],   (u64)vq.x, a0);
            a1 = ffma2(qpa[2*i+1], (u64)vq.y, a1);
            b0 = ffma2(qpb[2*i],   (u64)vq.x, b0);
            b1 = ffma2(qpb[2*i+1], (u64)vq.y, b1);
        }
        float2 x0 = unpk(a0), x1 = unpk(a1);
        float2 y0 = unpk(b0), y1 = unpk(b1);
        pa[j] = (x0.x + x0.y) + (x1.x + x1.y);
        pb[j] = (y0.x + y0.y) + (y1.x + y1.y);
    }
}

// Transpose partials across e, softmax over h, allgather weights across e.
__device__ __forceinline__ void softmaxw(
    float* __restrict__ pa, float* __restrict__ pb,
    bool elo1, bool elo2, float ebqA, float ebqB,
    float* __restrict__ wA, float* __restrict__ wB)
{
    {   // 4x4 e<->key transpose, stage 1 (partner e^1, lane xor 8)
        float a1v = elo1 ? pa[1] : pa[0];
        float a3v = elo1 ? pa[3] : pa[2];
        float b1v = elo1 ? pb[1] : pb[0];
        float b3v = elo1 ? pb[3] : pb[2];
        a1v = __shfl_xor_sync(0xffffffffu, a1v, 8);
        a3v = __shfl_xor_sync(0xffffffffu, a3v, 8);
        b1v = __shfl_xor_sync(0xffffffffu, b1v, 8);
        b3v = __shfl_xor_sync(0xffffffffu, b3v, 8);
        if (elo1) { pa[1] = a1v; pa[3] = a3v; pb[1] = b1v; pb[3] = b3v; }
        else      { pa[0] = a1v; pa[2] = a3v; pb[0] = b1v; pb[2] = b3v; }
    }
    {   // stage 2 (partner e^2, lane xor 16)
        float a2v = elo2 ? pa[2] : pa[0];
        float a3v = elo2 ? pa[3] : pa[1];
        float b2v = elo2 ? pb[2] : pb[0];
        float b3v = elo2 ? pb[3] : pb[1];
        a2v = __shfl_xor_sync(0xffffffffu, a2v, 16);
        a3v = __shfl_xor_sync(0xffffffffu, a3v, 16);
        b2v = __shfl_xor_sync(0xffffffffu, b2v, 16);
        b3v = __shfl_xor_sync(0xffffffffu, b3v, 16);
        if (elo2) { pa[2] = a2v; pa[3] = a3v; pb[2] = b2v; pb[3] = b3v; }
        else      { pa[0] = a2v; pa[1] = a3v; pb[0] = b2v; pb[1] = b3v; }
    }
    float sA = (pa[0] + pa[1]) + (pa[2] + pa[3]);  // full dot of key tt0+e
    float sB = (pb[0] + pb[1]) + (pb[2] + pb[3]);

    // Softmax over 8 heads (|s| small: no max-subtract needed)
    float exA = __expf(sA) * ebqA;
    float exB = __expf(sB) * ebqB;
    float smA = exA, smB = exB;
    smA += __shfl_xor_sync(0xffffffffu, smA, 1);
    smB += __shfl_xor_sync(0xffffffffu, smB, 1);
    smA += __shfl_xor_sync(0xffffffffu, smA, 2);
    smB += __shfl_xor_sync(0xffffffffu, smB, 2);
    smA += __shfl_xor_sync(0xffffffffu, smA, 4);
    smB += __shfl_xor_sync(0xffffffffu, smB, 4);
    wA[0] = __fdividef(exA, smA);   // weight of key tt0+e
    wB[0] = __fdividef(exB, smB);

    // Allgather across e: w[k] = weight of key tt0+(e^k)
    wA[1] = __shfl_xor_sync(0xffffffffu, wA[0], 8);
    wB[1] = __shfl_xor_sync(0xffffffffu, wB[0], 8);
    wA[2] = __shfl_xor_sync(0xffffffffu, wA[0], 16);
    wB[2] = __shfl_xor_sync(0xffffffffu, wB[0], 16);
    wA[3] = __shfl_xor_sync(0xffffffffu, wA[1], 16);
    wB[3] = __shfl_xor_sync(0xffffffffu, wB[1], 16);
}

// Phase B: rank-4 context update for both q-rows (V loaded once per chunk)
__device__ __forceinline__ void ctx4(
    const longlong2* __restrict__ Vs, int tt0, int e,
    const float* __restrict__ wA, const float* __restrict__ wB,
    u64* __restrict__ cta, u64* __restrict__ ctb)
{
    #pragma unroll
    for (int k = 0; k < 4; ++k) {
        u64 wpa = pk2(wA[k]);
        u64 wpb = pk2(wB[k]);
        const longlong2* vr = Vs + (tt0 + (e ^ k)) * 16;
        #pragma unroll
        for (int i = 0; i < 4; ++i) {
            longlong2 vq = vr[i * 4 + e];   // one LDS.128, 4 ffma2
            cta[2*i]   = ffma2(wpa, (u64)vq.x, cta[2*i]);
            cta[2*i+1] = ffma2(wpa, (u64)vq.y, cta[2*i+1]);
            ctb[2*i]   = ffma2(wpb, (u64)vq.x, ctb[2*i]);
            ctb[2*i+1] = ffma2(wpb, (u64)vq.y, ctb[2*i+1]);
        }
    }
}

__global__ __launch_bounds__(256, 2) void attn_kernel(
    const float* __restrict__ value,
    float* __restrict__ out)
{
    __shared__ __align__(16) float v_sh[2][KT * DH];   // 2 x 16 KB
    const int b  = blockIdx.y;
    const int q0 = blockIdx.x * TQ;
    const int t  = threadIdx.x;
    const int h  = t & 7;           // softmax group (8 heads)
    const int e  = (t >> 3) & 3;    // d-quarter / key-slot id
    const int ql = t >> 5;          // warp id 0..7
    const int rowA = b * TT + q0 + ql;
    const int rowB = rowA + 8;
    const bool elo1 = (e & 1) == 0;
    const bool elo2 = (e & 2) == 0;

    // Anti-lockstep skew: slot of this warp among the 4 co-resident on its
    // SMSP (2 warps from this block x 2 blocks/SM; adjacent blockIdx.x are
    // co-resident with high probability).
    const int dskew = ((ql >> 2) + ((blockIdx.x & 1) << 1)) * 16;
    float zsk = 1.0f;

    // Qp d-chunks (c = 4i+e) for both rows: 8 u64 each
    u64 qpa[8], qpb[8];
    {
        const longlong2* pa_ = (const longlong2*)(g_Qp + (size_t)rowA * DD + h * DH);
        const longlong2* pb_ = (const longlong2*)(g_Qp + (size_t)rowB * DD + h * DH);
        #pragma unroll
        for (int i = 0; i < 4; ++i) {
            longlong2 va = pa_[i * 4 + e];
            longlong2 vb = pb_[i * 4 + e];
            qpa[2*i] = (u64)va.x;  qpa[2*i+1] = (u64)va.y;
            qpb[2*i] = (u64)vb.x;  qpb[2*i+1] = (u64)vb.y;
        }
    }
    const float ebqA = __expf(g_bq[rowA * HH + h]);
    const float ebqB = __expf(g_bq[rowB * HH + h]);

    u64 cta[8], ctb[8];
    #pragma unroll
    for (int i = 0; i < 8; ++i) { cta[i] = 0ULL; ctb[i] = 0ULL; }

    const char* vbase = (const char*)(value + (size_t)b * TT * DH);
    const uint32_t sb[2] = { smem_u32(&v_sh[0][0]), smem_u32(&v_sh[1][0]) };

    // Prologue: stage tile 0 (16 KB: 4 x 16B per thread)
    {
        const char* src = vbase + t * 16;
        #pragma unroll
        for (int i = 0; i < 4; ++i)
            cp16(sb[0] + t * 16 + i * 4096, src + i * 4096);
        CP_COMMIT();
    }

    #pragma unroll 1
    for (int tile = 0; tile < NTILES; ++tile) {
        if (tile + 1 < NTILES) {
            const char* src = vbase + (size_t)(tile + 1) * (KT * DH * 4) + t * 16;
            uint32_t dbuf = sb[(tile + 1) & 1];
            #pragma unroll
            for (int i = 0; i < 4; ++i)
                cp16(dbuf + t * 16 + i * 4096, src + i * 4096);
            CP_COMMIT();
            CP_WAIT(1);
        } else {
            CP_WAIT(0);
        }
        __syncthreads();

        // ---- per-tile phase skew: ~230cyc x slot of dependent FMA chain ----
        #pragma unroll 1
        for (int i = 0; i < dskew; ++i)
            asm volatile("fma.rn.f32 %0, %0, %1, %2;"
                         : "+f"(zsk) : "f"(0.9999999f), "f"(1e-30f));

        const longlong2* Vs = (const longlong2*)&v_sh[tile & 1][0];

        #pragma unroll 1
        for (int tt0 = 0; tt0 < KT; tt0 += 4) {
            float pa[4], pb[4];
            dots4(Vs, tt0, e, qpa, qpb, pa, pb);

            float wA[4], wB[4];
            softmaxw(pa, pb, elo1, elo2, ebqA, ebqB, wA, wB);

            ctx4(Vs, tt0, e, wA, wB, cta, ctb);
        }
        __syncthreads();   // protect buffer before next prefetch overwrites it
    }

    // keep the skew chain alive without touching results
    asm volatile("" :: "f"(zsk));

    // out[b, q, h*64 + chunk(4i+e)] for both rows
    longlong2* opA = (longlong2*)(out + (size_t)rowA * DD + h * DH);
    longlong2* opB = (longlong2*)(out + (size_t)rowB * DD + h * DH);
    #pragma unroll
    for (int i = 0; i < 4; ++i) {
        longlong2 va, vb;
        va.x = (long long)cta[2*i];  va.y = (long long)cta[2*i+1];
        vb.x = (long long)ctb[2*i];  vb.y = (long long)ctb[2*i+1];
        opA[i * 4 + e] = va;
        opB[i * 4 + e] = vb;
    }
}

extern "C" void kernel_launch(void* const* d_in, const int* in_sizes, int n_in,
                              void* d_out, int out_size) {
    const float* query  = (const float*)d_in[0];   // [2,2048,512]
    const float* value  = (const float*)d_in[1];   // [2,2048,64]
    const float* conv_w = (const float*)d_in[2];   // [512,64,1]
    const float* conv_b = (const float*)d_in[3];   // [512]
    float* out = (float*)d_out;                    // [2,2048,512]

    prep_kernel<<<BB * TT / TQ1, 256>>>(query, conv_w, conv_b);
    dim3 grid(TT / TQ, BB);
    attn_kernel<<<grid, 256>>>(value, out);
}